// round 12
// baseline (speedup 1.0000x reference)
#include <cuda_runtime.h>
#include <math.h>

#define NROWS 32
#define NCOLS 512
#define NTILES 16                 // 512 / 32
#define NJOBS  136                // NTILES*(NTILES+1)/2
#define BLOCKS_X 17               // NJOBS / 8 warps per block
#define TOTAL_BLOCKS (BLOCKS_X * NROWS)   // 544
#define TSG 1024                  // g table size
#define G_MIN (-24.0f)
#define G_RANGE 64.0f             // g domain [-24, 40]
#define NB_TAU 8
#define NB_G 8
#define NB_W 6
#define W_FLOOR 0.001f
#define PDEG 10                   // polynomial coeff count (degree 9)

// ---------------- device scratch (no allocations allowed) ----------------
__device__ float2 d_tab_g[TSG];                // (g0, dg) lerp table
__device__ float  d_poly_tau[PDEG];            // monomial coeffs, tau(adr) on [0,1]
__device__ float  d_poly_w[PDEG];              // monomial coeffs, w-basis(adr) on [0,1]
__device__ float2 d_rs[NROWS * NCOLS];         // (r or NaN-if-masked, normalized s)
__device__ float  d_part_sum[TOTAL_BLOCKS];
__device__ float  d_part_cnt[TOTAL_BLOCKS];    // counts exact in float (< 2^24)
__device__ int    d_done;                      // last-block-done counter

// Chebyshev nodes on [0,1]: 0.5 + 0.5*cos(pi*(k+0.5)/10)
__device__ __constant__ float c_nodes[PDEG] = {
    0.9938441703f, 0.9455032621f, 0.8535533906f, 0.7269952499f, 0.5782172325f,
    0.4217827675f, 0.2730047501f, 0.1464466094f, 0.0544967379f, 0.0061558297f
};

// Monomial coefficients of shifted Chebyshev polys T*_n(x) = T_n(2x-1) on [0,1].
// cheb_mono[n][i] = coeff of x^i. Exact integers (hand-verified via recurrence).
__device__ __constant__ double cheb_mono[PDEG][PDEG] = {
    {  1,    0,     0,      0,       0,       0,        0,        0,       0,      0},
    { -1,    2,     0,      0,       0,       0,        0,        0,       0,      0},
    {  1,   -8,     8,      0,       0,       0,        0,        0,       0,      0},
    { -1,   18,   -48,     32,       0,       0,        0,        0,       0,      0},
    {  1,  -32,   160,   -256,     128,       0,        0,        0,       0,      0},
    { -1,   50,  -400,   1120,   -1280,     512,        0,        0,       0,      0},
    {  1,  -72,   840,  -3584,    6912,   -6144,     2048,        0,       0,      0},
    { -1,   98, -1568,   9408,  -26880,   39424,   -28672,     8192,       0,      0},
    {  1, -128,  2688, -21504,   84480, -180224,   212992,  -131072,   32768,      0},
    { -1,  162, -4320,  44352, -228096,  658944, -1118208,  1105920, -589824, 131072}
};

// fast-math activations (float only; rel_err budget ~1e-3)
__device__ __forceinline__ float fsp(float z) {
    return fmaxf(z, 0.0f) + __logf(1.0f + __expf(-fabsf(z)));
}
__device__ __forceinline__ float fsg(float z) {
    return __fdividef(1.0f, 1.0f + __expf(-z));
}

// packed f32x2 helpers (sm_103a FFMA2 path; PTX-only per SASS spec)
__device__ __forceinline__ unsigned long long pack2(float lo, float hi) {
    unsigned long long r;
    asm("mov.b64 %0, {%1, %2};" : "=l"(r) : "f"(lo), "f"(hi));
    return r;
}
__device__ __forceinline__ void unpack2(unsigned long long v, float& lo, float& hi) {
    asm("mov.b64 {%0, %1}, %2;" : "=f"(lo), "=f"(hi) : "l"(v));
}
__device__ __forceinline__ unsigned long long ffma2(
    unsigned long long a, unsigned long long b, unsigned long long c) {
    unsigned long long d;
    asm("fma.rn.f32x2 %0, %1, %2, %3;" : "=l"(d) : "l"(a), "l"(b), "l"(c));
    return d;
}

// ---------------- kernel A: g table + normalization + DCT poly fit ----------
// blocks 0..7 : g lerp table (128 entries each)
// blocks 8..15: row normalization (4 rows per block, 1 warp per row)
// block 16    : Chebyshev DCT fit, 20 parallel threads, NO spilled arrays,
//               NO serial fp64 chains (R10/R11's setup bug)
__global__ void __launch_bounds__(128) setup_kernel(
    const float* __restrict__ pred, const float* __restrict__ tg,
    const float* __restrict__ th_tau, const float* __restrict__ th_g,
    const float* __restrict__ th_w)
{
    __shared__ float sh_c[2][PDEG];
    int tid = threadIdx.x;
    int bx  = blockIdx.x;
    if (bx < 8) {
        int i = bx * 128 + tid;   // 0..1023
        float cg[NB_G];
#pragma unroll
        for (int u = 0; u < NB_G; u++) cg[u] = fsp(th_g[u]);
        float h = G_RANGE / (float)(TSG - 1);
        float x = G_MIN + (float)i * h;
        float v0 = 0.f, v1 = 0.f;
#pragma unroll
        for (int u = 0; u < NB_G; u++) {
            float sl = 0.5f + 3.5f * (float)u / (float)(NB_G - 1);
            float bi = -2.0f + 4.0f * (float)u / (float)(NB_G - 1);
            v0 += cg[u] * fsp(fmaf(x,     sl, bi));
            v1 += cg[u] * fsp(fmaf(x + h, sl, bi));
        }
        d_tab_g[i] = make_float2(v0, v1 - v0);
    } else if (bx < 16) {
        // one warp per row: masked mean/var normalization, write d_rs
        int w = (bx - 8) * 4 + (tid >> 5), lane = tid & 31;
        const float* p = pred + w * NCOLS;
        const float* t = tg   + w * NCOLS;
        float lp[16], lt[16]; bool lm[16];
        float sum = 0.0f, ssq = 0.0f, cnt = 0.0f;
#pragma unroll
        for (int u = 0; u < 16; u++) {
            float tv = t[lane + 32 * u];
            bool  m  = fabsf(tv + 1.0f) > 1.00001e-5f;   // ~jnp.isclose(t,-1) negated
            float pv = p[lane + 32 * u];
            lp[u] = pv; lt[u] = tv; lm[u] = m;
            sum += m ? pv : 0.0f;
            ssq += m ? pv * pv : 0.0f;
            cnt += m ? 1.0f : 0.0f;
        }
#pragma unroll
        for (int o = 16; o; o >>= 1) {
            sum += __shfl_xor_sync(0xffffffffu, sum, o);
            ssq += __shfl_xor_sync(0xffffffffu, ssq, o);
            cnt += __shfl_xor_sync(0xffffffffu, cnt, o);
        }
        float denom = fmaxf(cnt, 1.0f);
        float mean  = sum / denom;
        float var   = ssq / denom - mean * mean;
        float inv   = rsqrtf(var + 1e-6f);
        const float qnan = __int_as_float(0x7fffffff);
#pragma unroll
        for (int u = 0; u < 16; u++)
            d_rs[w * NCOLS + lane + 32 * u] =
                make_float2(lm[u] ? lt[u] : qnan, (lp[u] - mean) * inv);
    } else {
        // --- DCT fit: threads 0..19, pid = tid/10 (0=tau softplus, 1=w sigmoid)
        int pid = tid / PDEG;
        int n   = tid % PDEG;
        if (tid < 2 * PDEG) {
            const int nb = (pid == 0) ? NB_TAU : NB_W;
            const float* th = (pid == 0) ? th_tau : th_w;
            float c[8];
#pragma unroll
            for (int i = 0; i < 8; i++) c[i] = (i < nb) ? fsp(th[i]) : 0.0f;
            float cn = 0.0f;
#pragma unroll
            for (int k = 0; k < PDEG; k++) {
                float x = c_nodes[k];
                float fk = 0.0f;
                for (int i = 0; i < nb; i++) {
                    float sl = 0.5f + 3.5f * (float)i / (float)(nb - 1);
                    float bi = -2.0f + 4.0f * (float)i / (float)(nb - 1);
                    float z  = fmaf(x, sl, bi);
                    fk += c[i] * ((pid == 0) ? fsp(z) : fsg(z));
                }
                cn += fk * __cosf((float)(n * (2 * k + 1)) * 0.15707963268f); // pi/20
            }
            sh_c[pid][n] = cn * ((n == 0) ? 0.1f : 0.2f);
        }
        __syncthreads();
        if (tid < 2 * PDEG) {
            int i = n;   // monomial coefficient index
            double mc = 0.0;
#pragma unroll
            for (int nn = 0; nn < PDEG; nn++)
                mc += (double)sh_c[pid][nn] * cheb_mono[nn][i];
            float* dst = (pid == 0) ? d_poly_tau : d_poly_w;
            dst[i] = (float)mc;
        }
    }
}

// ---------------- kernel B: tiled pair loop + final (fused) ------------------
__global__ void __launch_bounds__(256) pair_kernel(float* __restrict__ out) {
    __shared__ float2 sh_g[TSG];       // 8 KB
    __shared__ float2 sh_rs[NCOLS];    // 4 KB
    __shared__ float  red_f[8];
    __shared__ float  red_c[8];
    __shared__ int    sh_last;
    __shared__ float  s_num[32];
    __shared__ float  s_val[32];

    int tid  = threadIdx.x;
    int b    = blockIdx.y;
    int lane = tid & 31, warp = tid >> 5;

    // ---- prologue: bulk float4 copy of g table + this row (12 KB) ----
    {
        const float4* sg = (const float4*)d_tab_g;            float4* dg = (float4*)sh_g;
        const float4* sr = (const float4*)(d_rs + b * NCOLS); float4* dr = (float4*)sh_rs;
        dg[tid] = sg[tid]; dg[tid + 256] = sg[tid + 256];     // 512 float4
        dr[tid] = sr[tid];                                    // 256 float4
    }
    // packed (tau, w) poly coeffs -> registers
    unsigned long long pk[PDEG];
#pragma unroll
    for (int u = 0; u < PDEG; u++) pk[u] = pack2(d_poly_tau[u], d_poly_w[u]);
    __syncthreads();

    // ---- one 32x32 tile job per warp ----
    // jobs enumerate 0 <= ti <= tj < 16; diagonal tiles keep ii < lane.
    // Pair loss is symmetric under (i,j) swap so orientation is irrelevant.
    int jb = blockIdx.x * 8 + warp;   // 0 .. 135
    int ti = 0, rem = jb;
    while (rem >= NTILES - ti) { rem -= NTILES - ti; ti++; }
    int tj  = ti + rem;
    int lim = (ti == tj) ? lane : 32;

    float2 pj = sh_rs[tj * 32 + lane];    // register-resident j side
    const int ibase = ti * 32;
    const float inv_hg = (float)(TSG - 1) / G_RANGE;
    const float c0     = -G_MIN * inv_hg;

    float acc = 0.0f, cntf = 0.0f;
#pragma unroll 4
    for (int ii = 0; ii < 32; ii++) {
        float2 pi = sh_rs[ibase + ii];    // uniform address -> broadcast LDS.64
        float dr = pi.x - pj.x;
        float ds = pi.y - pj.y;
        // branchless keep: false for ties and NaN (masked rows)
        float kf = (((dr > 0.0f) | (dr < 0.0f)) & (ii < lim)) ? 1.0f : 0.0f;
        float tds = (dr > 0.0f) ? ds : -ds;              // t * ds
        float t   = fminf(fabsf(dr), 1.0f);              // fminf(NaN,1)=1 -> safe
        // tau & w via ONE packed f32x2 Horner chain (9 FFMA2)
        unsigned long long tt = pack2(t, t);
        unsigned long long h  = pk[PDEG - 1];
#pragma unroll
        for (int u = PDEG - 2; u >= 0; u--) h = ffma2(h, tt, pk[u]);
        float tau, w;
        unpack2(h, tau, w);
        w += W_FLOOR;
        float m   = tau - tds;
        float pg  = fmaxf(fmaf(m, inv_hg, c0), 0.0f);
        int   ig  = min((int)pg, TSG - 2);
        float fg  = pg - (float)ig;                      // frac>1 at top = exact linear ext
        float2 eg = sh_g[ig];                            // one LDS.64 gather
        float g   = fmaf(fg, eg.y, eg.x);
        acc  = fmaf(kf, g * w, acc);
        cntf += kf;
    }

#pragma unroll
    for (int o = 16; o; o >>= 1) {
        acc  += __shfl_xor_sync(0xffffffffu, acc, o);
        cntf += __shfl_xor_sync(0xffffffffu, cntf, o);
    }
    if (lane == 0) { red_f[warp] = acc; red_c[warp] = cntf; }
    __syncthreads();
    if (tid == 0) {
        float bs = 0.0f, bc = 0.0f;
#pragma unroll
        for (int u = 0; u < 8; u++) { bs += red_f[u]; bc += red_c[u]; }
        int slot = b * BLOCKS_X + blockIdx.x;
        d_part_sum[slot] = bs;
        d_part_cnt[slot] = bc;
        __threadfence();
        int old = atomicAdd(&d_done, 1);
        sh_last = (old == TOTAL_BLOCKS - 1) ? 1 : 0;
    }
    __syncthreads();

    // ---- last block performs the final reduction (544 partials) ----
    if (sh_last) {
        __threadfence();   // acquire: partials of all other blocks now visible
        volatile float* vs = d_part_sum;
        volatile float* vc = d_part_cnt;
        int row = tid >> 3;            // 32 rows x 8 lanes
        int sub = tid & 7;
        int base = row * BLOCKS_X;
        float ps = 0.0f, pc = 0.0f;
        for (int k = sub; k < BLOCKS_X; k += 8) { ps += vs[base + k]; pc += vc[base + k]; }
#pragma unroll
        for (int o = 4; o; o >>= 1) {
            ps += __shfl_xor_sync(0xffffffffu, ps, o);
            pc += __shfl_xor_sync(0xffffffffu, pc, o);
        }
        if (sub == 0) {
            float denom = fmaxf(pc, 1.0f);
            float rl    = ps / denom;
            float valid = (pc > 0.0f) ? 1.0f : 0.0f;
            s_num[row] = rl * valid;
            s_val[row] = valid;
        }
        __syncthreads();
        if (tid < 32) {
            float n = s_num[tid], v = s_val[tid];
#pragma unroll
            for (int o = 16; o; o >>= 1) {
                n += __shfl_xor_sync(0xffffffffu, n, o);
                v += __shfl_xor_sync(0xffffffffu, v, o);
            }
            if (tid == 0) {
                out[0] = n / fmaxf(v, 1.0f);
                d_done = 0;            // reset for next graph replay (deterministic)
            }
        }
    }
}

// ---------------- launch ----------------
extern "C" void kernel_launch(void* const* d_in, const int* in_sizes, int n_in,
                              void* d_out, int out_size) {
    const float* pred   = (const float*)d_in[0];
    const float* tg     = (const float*)d_in[1];
    const float* th_tau = (const float*)d_in[2];
    const float* th_g   = (const float*)d_in[3];
    const float* th_w   = (const float*)d_in[4];

    setup_kernel<<<17, 128>>>(pred, tg, th_tau, th_g, th_w);
    dim3 grid(BLOCKS_X, NROWS);
    pair_kernel<<<grid, 256>>>((float*)d_out);
}

// round 13
// speedup vs baseline: 2.4830x; 2.4830x over previous
#include <cuda_runtime.h>
#include <math.h>
#include <cmath>

#define NROWS 32
#define NCOLS 512
#define NTILES 16                 // 512 / 32
#define NJOBS  136                // NTILES*(NTILES+1)/2
#define BLOCKS_X 17               // NJOBS / 8 warps per block
#define TOTAL_BLOCKS (BLOCKS_X * NROWS)   // 544
#define TSG 1024                  // g table size
#define G_MIN (-24.0f)
#define G_RANGE 64.0f             // g domain [-24, 40]
#define NB_TAU 8
#define NB_G 8
#define NB_W 6
#define W_FLOOR 0.001f
#define PDEG 10                   // polynomial coeff count (degree 9)

// Constant linear map from softplus(theta) to monomial poly coeffs, computed
// on the HOST in double (basis slopes/biases are compile-time constants) and
// passed by value as a kernel parameter. Baked into the graph at capture.
struct FitMats {
    float bt[PDEG][NB_TAU];   // poly_tau[m] = sum_i bt[m][i] * softplus(th_tau[i])
    float bw[PDEG][NB_W];     // poly_w[m]   = sum_i bw[m][i] * softplus(th_w[i])
};

// ---------------- device scratch (no allocations allowed) ----------------
__device__ float2 d_tab_g[TSG];                // (g0, dg) lerp table
__device__ float  d_poly_tau[PDEG];            // monomial coeffs, tau(adr) on [0,1]
__device__ float  d_poly_w[PDEG];              // monomial coeffs, w-basis(adr) on [0,1]
__device__ float2 d_rs[NROWS * NCOLS];         // (r or NaN-if-masked, normalized s)
__device__ float  d_part_sum[TOTAL_BLOCKS];
__device__ float  d_part_cnt[TOTAL_BLOCKS];    // counts exact in float (< 2^24)
__device__ int    d_done;                      // last-block-done counter

// fast-math activations (float only; rel_err budget ~1e-3)
__device__ __forceinline__ float fsp(float z) {
    return fmaxf(z, 0.0f) + __logf(1.0f + __expf(-fabsf(z)));
}

// packed f32x2 helpers (sm_103a FFMA2 path; PTX-only per SASS spec)
__device__ __forceinline__ unsigned long long pack2(float lo, float hi) {
    unsigned long long r;
    asm("mov.b64 %0, {%1, %2};" : "=l"(r) : "f"(lo), "f"(hi));
    return r;
}
__device__ __forceinline__ void unpack2(unsigned long long v, float& lo, float& hi) {
    asm("mov.b64 {%0, %1}, %2;" : "=f"(lo), "=f"(hi) : "l"(v));
}
__device__ __forceinline__ unsigned long long ffma2(
    unsigned long long a, unsigned long long b, unsigned long long c) {
    unsigned long long d;
    asm("fma.rn.f32x2 %0, %1, %2, %3;" : "=l"(d) : "l"(a), "l"(b), "l"(c));
    return d;
}

// ---------------- kernel A: g table + normalization + trivial fit -----------
// blocks 0..7 : g lerp table (128 entries each)
// blocks 8..15: row normalization (4 rows per block, 1 warp per row)
// block 16    : poly coeffs = constant matrix (host-computed) x softplus(theta)
__global__ void __launch_bounds__(128) setup_kernel(
    const float* __restrict__ pred, const float* __restrict__ tg,
    const float* __restrict__ th_tau, const float* __restrict__ th_g,
    const float* __restrict__ th_w, FitMats P)
{
    int tid = threadIdx.x;
    int bx  = blockIdx.x;
    if (bx < 8) {
        int i = bx * 128 + tid;   // 0..1023
        float cg[NB_G];
#pragma unroll
        for (int u = 0; u < NB_G; u++) cg[u] = fsp(th_g[u]);
        float h = G_RANGE / (float)(TSG - 1);
        float x = G_MIN + (float)i * h;
        float v0 = 0.f, v1 = 0.f;
#pragma unroll
        for (int u = 0; u < NB_G; u++) {
            float sl = 0.5f + 3.5f * (float)u / (float)(NB_G - 1);
            float bi = -2.0f + 4.0f * (float)u / (float)(NB_G - 1);
            v0 += cg[u] * fsp(fmaf(x,     sl, bi));
            v1 += cg[u] * fsp(fmaf(x + h, sl, bi));
        }
        d_tab_g[i] = make_float2(v0, v1 - v0);
    } else if (bx < 16) {
        // one warp per row: masked mean/var normalization, write d_rs
        int w = (bx - 8) * 4 + (tid >> 5), lane = tid & 31;
        const float* p = pred + w * NCOLS;
        const float* t = tg   + w * NCOLS;
        float lp[16], lt[16]; bool lm[16];
        float sum = 0.0f, ssq = 0.0f, cnt = 0.0f;
#pragma unroll
        for (int u = 0; u < 16; u++) {
            float tv = t[lane + 32 * u];
            bool  m  = fabsf(tv + 1.0f) > 1.00001e-5f;   // ~jnp.isclose(t,-1) negated
            float pv = p[lane + 32 * u];
            lp[u] = pv; lt[u] = tv; lm[u] = m;
            sum += m ? pv : 0.0f;
            ssq += m ? pv * pv : 0.0f;
            cnt += m ? 1.0f : 0.0f;
        }
#pragma unroll
        for (int o = 16; o; o >>= 1) {
            sum += __shfl_xor_sync(0xffffffffu, sum, o);
            ssq += __shfl_xor_sync(0xffffffffu, ssq, o);
            cnt += __shfl_xor_sync(0xffffffffu, cnt, o);
        }
        float denom = fmaxf(cnt, 1.0f);
        float mean  = sum / denom;
        float var   = ssq / denom - mean * mean;
        float inv   = rsqrtf(var + 1e-6f);
        const float qnan = __int_as_float(0x7fffffff);
#pragma unroll
        for (int u = 0; u < 16; u++)
            d_rs[w * NCOLS + lane + 32 * u] =
                make_float2(lm[u] ? lt[u] : qnan, (lp[u] - mean) * inv);
    } else if (tid < 2 * PDEG) {
        // trivial fit: dot product with host-computed constant matrix
        int pid = tid / PDEG, m = tid % PDEG;
        float s = 0.0f;
        if (pid == 0) {
#pragma unroll
            for (int i = 0; i < NB_TAU; i++) s += fsp(th_tau[i]) * P.bt[m][i];
            d_poly_tau[m] = s;
        } else {
#pragma unroll
            for (int i = 0; i < NB_W; i++) s += fsp(th_w[i]) * P.bw[m][i];
            d_poly_w[m] = s;
        }
    }
}

// ---------------- kernel B: tiled pair loop + final (fused) ------------------
__global__ void __launch_bounds__(256) pair_kernel(float* __restrict__ out) {
    __shared__ float2 sh_g[TSG];       // 8 KB
    __shared__ float2 sh_rs[NCOLS];    // 4 KB
    __shared__ float  red_f[8];
    __shared__ float  red_c[8];
    __shared__ int    sh_last;
    __shared__ float  s_num[32];
    __shared__ float  s_val[32];

    int tid  = threadIdx.x;
    int b    = blockIdx.y;
    int lane = tid & 31, warp = tid >> 5;

    // ---- prologue: bulk float4 copy of g table + this row (12 KB) ----
    {
        const float4* sg = (const float4*)d_tab_g;            float4* dg = (float4*)sh_g;
        const float4* sr = (const float4*)(d_rs + b * NCOLS); float4* dr = (float4*)sh_rs;
        dg[tid] = sg[tid]; dg[tid + 256] = sg[tid + 256];     // 512 float4
        dr[tid] = sr[tid];                                    // 256 float4
    }
    // packed (tau, w) poly coeffs -> registers
    unsigned long long pk[PDEG];
#pragma unroll
    for (int u = 0; u < PDEG; u++) pk[u] = pack2(d_poly_tau[u], d_poly_w[u]);
    __syncthreads();

    // ---- one 32x32 tile job per warp ----
    // jobs enumerate 0 <= ti <= tj < 16; diagonal tiles keep ii < lane.
    // Pair loss is symmetric under (i,j) swap so orientation is irrelevant.
    int jb = blockIdx.x * 8 + warp;   // 0 .. 135
    int ti = 0, rem = jb;
    while (rem >= NTILES - ti) { rem -= NTILES - ti; ti++; }
    int tj  = ti + rem;
    int lim = (ti == tj) ? lane : 32;

    float2 pj = sh_rs[tj * 32 + lane];    // register-resident j side
    const int ibase = ti * 32;
    const float inv_hg = (float)(TSG - 1) / G_RANGE;
    const float c0     = -G_MIN * inv_hg;

    float acc = 0.0f, cntf = 0.0f;
#pragma unroll 4
    for (int ii = 0; ii < 32; ii++) {
        float2 pi = sh_rs[ibase + ii];    // uniform address -> broadcast LDS.64
        float dr = pi.x - pj.x;
        float ds = pi.y - pj.y;
        float adr = fabsf(dr);
        // keep: ordered compare -> false for ties AND NaN (masked rows)
        float kf = ((adr > 0.0f) & (ii < lim)) ? 1.0f : 0.0f;
        // t * ds via sign-bit transfer (LOP3 instead of FSETP+SEL)
        float tds = __int_as_float(__float_as_int(ds) ^
                                   (__float_as_int(dr) & 0x80000000));
        float t   = fminf(adr, 1.0f);                    // fminf(NaN,1)=1 -> safe
        // tau & w via ONE packed f32x2 Horner chain (9 FFMA2)
        unsigned long long tt = pack2(t, t);
        unsigned long long h  = pk[PDEG - 1];
#pragma unroll
        for (int u = PDEG - 2; u >= 0; u--) h = ffma2(h, tt, pk[u]);
        float tau, w;
        unpack2(h, tau, w);
        w += W_FLOOR;
        float m   = tau - tds;
        float pg  = fmaxf(fmaf(m, inv_hg, c0), 0.0f);    // fmaxf(NaN,0)=0 -> safe idx
        int   ig  = min((int)pg, TSG - 2);
        float fg  = pg - (float)ig;                      // frac>1 at top = exact linear ext
        float2 eg = sh_g[ig];                            // one LDS.64 gather
        float g   = fmaf(fg, eg.y, eg.x);
        acc  = fmaf(kf, g * w, acc);
        cntf += kf;
    }

#pragma unroll
    for (int o = 16; o; o >>= 1) {
        acc  += __shfl_xor_sync(0xffffffffu, acc, o);
        cntf += __shfl_xor_sync(0xffffffffu, cntf, o);
    }
    if (lane == 0) { red_f[warp] = acc; red_c[warp] = cntf; }
    __syncthreads();
    if (tid == 0) {
        float bs = 0.0f, bc = 0.0f;
#pragma unroll
        for (int u = 0; u < 8; u++) { bs += red_f[u]; bc += red_c[u]; }
        int slot = b * BLOCKS_X + blockIdx.x;
        d_part_sum[slot] = bs;
        d_part_cnt[slot] = bc;
        __threadfence();
        int old = atomicAdd(&d_done, 1);
        sh_last = (old == TOTAL_BLOCKS - 1) ? 1 : 0;
    }
    __syncthreads();

    // ---- last block performs the final reduction (544 partials) ----
    if (sh_last) {
        __threadfence();   // acquire: partials of all other blocks now visible
        volatile float* vs = d_part_sum;
        volatile float* vc = d_part_cnt;
        int row = tid >> 3;            // 32 rows x 8 lanes
        int sub = tid & 7;
        int base = row * BLOCKS_X;
        float ps = 0.0f, pc = 0.0f;
        for (int k = sub; k < BLOCKS_X; k += 8) { ps += vs[base + k]; pc += vc[base + k]; }
#pragma unroll
        for (int o = 4; o; o >>= 1) {
            ps += __shfl_xor_sync(0xffffffffu, ps, o);
            pc += __shfl_xor_sync(0xffffffffu, pc, o);
        }
        if (sub == 0) {
            float denom = fmaxf(pc, 1.0f);
            float rl    = ps / denom;
            float valid = (pc > 0.0f) ? 1.0f : 0.0f;
            s_num[row] = rl * valid;
            s_val[row] = valid;
        }
        __syncthreads();
        if (tid < 32) {
            float n = s_num[tid], v = s_val[tid];
#pragma unroll
            for (int o = 16; o; o >>= 1) {
                n += __shfl_xor_sync(0xffffffffu, n, o);
                v += __shfl_xor_sync(0xffffffffu, v, o);
            }
            if (tid == 0) {
                out[0] = n / fmaxf(v, 1.0f);
                d_done = 0;            // reset for next graph replay (deterministic)
            }
        }
    }
}

// ---------------- host-side fit matrix construction --------------------------
// Monomial coefficients of shifted Chebyshev T*_n(x) = T_n(2x-1): exact ints.
static const double h_cheb_mono[PDEG][PDEG] = {
    {  1,    0,     0,      0,       0,       0,        0,        0,       0,      0},
    { -1,    2,     0,      0,       0,       0,        0,        0,       0,      0},
    {  1,   -8,     8,      0,       0,       0,        0,        0,       0,      0},
    { -1,   18,   -48,     32,       0,       0,        0,        0,       0,      0},
    {  1,  -32,   160,   -256,     128,       0,        0,        0,       0,      0},
    { -1,   50,  -400,   1120,   -1280,     512,        0,        0,       0,      0},
    {  1,  -72,   840,  -3584,    6912,   -6144,     2048,        0,       0,      0},
    { -1,   98, -1568,   9408,  -26880,   39424,   -28672,     8192,       0,      0},
    {  1, -128,  2688, -21504,   84480, -180224,   212992,  -131072,   32768,      0},
    { -1,  162, -4320,  44352, -228096,  658944, -1118208,  1105920, -589824, 131072}
};

static void host_fit_basis(double sl, double bi, bool is_sigmoid, double* bcol /*[PDEG]*/) {
    // degree-9 Chebyshev interpolation of basis(sl*x+bi) on [0,1] -> monomial
    double xs[PDEG], f[PDEG];
    for (int k = 0; k < PDEG; k++) {
        xs[k] = 0.5 + 0.5 * cos(M_PI * (k + 0.5) / PDEG);
        double z = xs[k] * sl + bi;
        f[k] = is_sigmoid ? 1.0 / (1.0 + exp(-z))
                          : ((z > 0.0) ? z + log1p(exp(-z)) : log1p(exp(z)));
    }
    double a[PDEG];
    for (int n = 0; n < PDEG; n++) {
        double s = 0.0;
        for (int k = 0; k < PDEG; k++)
            s += f[k] * cos(M_PI * n * (2 * k + 1) / (2.0 * PDEG));
        a[n] = s * ((n == 0) ? (1.0 / PDEG) : (2.0 / PDEG));
    }
    for (int m = 0; m < PDEG; m++) {
        double s = 0.0;
        for (int n = 0; n < PDEG; n++) s += a[n] * h_cheb_mono[n][m];
        bcol[m] = s;
    }
}

static void build_fit_mats(FitMats* F) {
    double col[PDEG];
    for (int i = 0; i < NB_TAU; i++) {
        double sl = 0.5 + 3.5 * (double)i / (double)(NB_TAU - 1);
        double bi = -2.0 + 4.0 * (double)i / (double)(NB_TAU - 1);
        host_fit_basis(sl, bi, false, col);
        for (int m = 0; m < PDEG; m++) F->bt[m][i] = (float)col[m];
    }
    for (int i = 0; i < NB_W; i++) {
        double sl = 0.5 + 3.5 * (double)i / (double)(NB_W - 1);
        double bi = -2.0 + 4.0 * (double)i / (double)(NB_W - 1);
        host_fit_basis(sl, bi, true, col);
        for (int m = 0; m < PDEG; m++) F->bw[m][i] = (float)col[m];
    }
}

// ---------------- launch ----------------
extern "C" void kernel_launch(void* const* d_in, const int* in_sizes, int n_in,
                              void* d_out, int out_size) {
    const float* pred   = (const float*)d_in[0];
    const float* tg     = (const float*)d_in[1];
    const float* th_tau = (const float*)d_in[2];
    const float* th_g   = (const float*)d_in[3];
    const float* th_w   = (const float*)d_in[4];

    FitMats F;                 // host-computed, deterministic; baked into graph
    build_fit_mats(&F);

    setup_kernel<<<17, 128>>>(pred, tg, th_tau, th_g, th_w, F);
    dim3 grid(BLOCKS_X, NROWS);
    pair_kernel<<<grid, 256>>>((float*)d_out);
}